// round 5
// baseline (speedup 1.0000x reference)
#include <cuda_runtime.h>
#include <cuda_bf16.h>
#include <cstdint>

#define B_  32
#define NN  512
#define TT  24
#define FF  64
#define FA  74
#define TF  1536      // TT*FF
#define OUTROW 1776   // TT*FA

#define BM 128
#define BN 128
#define BK 64
#define NKS (NN / BK)  // 8
#define STAGES 3

#define AROWB 144       // A row bytes in smem (128 data + 16 pad)
#define BROWB 272       // B row bytes in smem (256 data + 16 pad)
#define ASTGB (BM * AROWB)            // 18432
#define BSTGB (BK * BROWB)            // 17408
#define STAGEB (ASTGB + BSTGB)        // 35840
#define GEMM_SMEM (STAGES * STAGEB)   // 107520

__device__ float g_RW[FA];
__device__ float g_W2[TT * TT];
__device__ float g_sigA[NN];
__device__ __nv_bfloat16 g_xb[(size_t)B_ * NN * TF];
__device__ __nv_bfloat16 g_adjb[(size_t)NN * NN];

// ---------------------------------------------------------------------------
__device__ __forceinline__ uint32_t smem_u32(const void* p) {
    uint32_t a;
    asm("{ .reg .u64 t; cvta.to.shared.u64 t, %1; cvt.u32.u64 %0, t; }" : "=r"(a) : "l"(p));
    return a;
}
__device__ __forceinline__ void ldsm4(uint32_t* r, uint32_t addr) {
    asm volatile("ldmatrix.sync.aligned.m8n8.x4.shared.b16 {%0,%1,%2,%3}, [%4];"
                 : "=r"(r[0]), "=r"(r[1]), "=r"(r[2]), "=r"(r[3]) : "r"(addr));
}
__device__ __forceinline__ void ldsm4t(uint32_t* r, uint32_t addr) {
    asm volatile("ldmatrix.sync.aligned.m8n8.x4.trans.shared.b16 {%0,%1,%2,%3}, [%4];"
                 : "=r"(r[0]), "=r"(r[1]), "=r"(r[2]), "=r"(r[3]) : "r"(addr));
}
__device__ __forceinline__ void mma16816(float* c, const uint32_t* a, const uint32_t* b) {
    asm volatile(
        "mma.sync.aligned.m16n8k16.row.col.f32.bf16.bf16.f32 "
        "{%0,%1,%2,%3}, {%4,%5,%6,%7}, {%8,%9}, {%0,%1,%2,%3};"
        : "+f"(c[0]), "+f"(c[1]), "+f"(c[2]), "+f"(c[3])
        : "r"(a[0]), "r"(a[1]), "r"(a[2]), "r"(a[3]), "r"(b[0]), "r"(b[1]));
}
#define CP16(dst, src) \
    asm volatile("cp.async.cg.shared.global [%0], [%1], 16;" :: "r"(dst), "l"(src) : "memory")
#define CP_COMMIT() asm volatile("cp.async.commit_group;" ::: "memory")
#define CP_WAIT1()  asm volatile("cp.async.wait_group 1;" ::: "memory")

// ---------------------------------------------------------------------------
// Prep: RW, W2eff, sigmoid(alpha)
// ---------------------------------------------------------------------------
__global__ void prep_kernel(const float* __restrict__ alpha,
                            const float* __restrict__ w,
                            const float* __restrict__ d,
                            const float* __restrict__ w2,
                            const float* __restrict__ d2) {
    __shared__ float colsum[FA];
    __shared__ float dc[FA];
    int tid = threadIdx.x;  // 256

    for (int n = tid; n < NN; n += 256)
        g_sigA[n] = 1.0f / (1.0f + expf(-alpha[n]));

    if (tid < FA) {
        float s = 0.f;
        for (int n = 0; n < FA; n++) s += w[n * FA + tid];
        colsum[tid] = s;
        dc[tid] = fminf(fmaxf(d[tid], 0.f), 1.f);
    }
    __syncthreads();
    if (tid < FA) {
        float s = 0.f;
        for (int k = 0; k < FA; k++) s += w[tid * FA + k] * dc[k] * colsum[k];
        g_RW[tid] = s;
    }
    for (int idx = tid; idx < TT * TT; idx += 256) {
        int t = idx / TT, tp = idx % TT;
        float s = 0.f;
        for (int k = 0; k < TT; k++) {
            float dk = fminf(fmaxf(d2[k], 0.f), 1.f);
            s += w2[t * TT + k] * dk * w2[tp * TT + k];
        }
        g_W2[idx] = s;
    }
}

__global__ void convert_adj_kernel(const float* __restrict__ adj) {
    size_t i = (size_t)blockIdx.x * 256 + threadIdx.x;
    const float4* src = (const float4*)adj + i * 2;
    float4 a = src[0], b = src[1];
    __nv_bfloat162 h0 = __float22bfloat162_rn(make_float2(a.x, a.y));
    __nv_bfloat162 h1 = __float22bfloat162_rn(make_float2(a.z, a.w));
    __nv_bfloat162 h2 = __float22bfloat162_rn(make_float2(b.x, b.y));
    __nv_bfloat162 h3 = __float22bfloat162_rn(make_float2(b.z, b.w));
    ((uint4*)g_adjb)[i] = make_uint4(*(uint32_t*)&h0, *(uint32_t*)&h1,
                                     *(uint32_t*)&h2, *(uint32_t*)&h3);
}

// ---------------------------------------------------------------------------
// basex: per (b,n) row — convert x->bf16 (for GEMM) AND write base terms:
//   out[t,f<64]  = 0.5*x + 0.25*xw2 + 0.25*S*RW      (raw; GEMM epilogue relu's)
//   out[t,f>=64] = relu(0.25*S*RW[f])                 (final)
// ---------------------------------------------------------------------------
__global__ __launch_bounds__(128)
void basex_kernel(const float* __restrict__ x, float* __restrict__ out) {
    int row = blockIdx.x;                // b*NN + node
    const float* xr = x + (size_t)row * TF;
    float* outr = out + (size_t)row * OUTROW;
    __nv_bfloat16* xbr = g_xb + (size_t)row * TF;

    __shared__ float xs[TF];
    __shared__ float W2s[TT * TT];
    __shared__ float S[TT];
    __shared__ float RWs[FA];

    int tid = threadIdx.x;  // 128
    #pragma unroll
    for (int j = 0; j < 3; j++)
        ((float4*)xs)[j * 128 + tid] = ((const float4*)xr)[j * 128 + tid];
    for (int j = tid; j < TT * TT; j += 128) W2s[j] = g_W2[j];
    if (tid < FA) RWs[tid] = g_RW[tid];
    __syncthreads();

    // write bf16 copy for the GEMM
    #pragma unroll
    for (int j = 0; j < 3; j++) {
        int idx = j * 128 + tid;
        float4 v = ((const float4*)xs)[idx];
        __nv_bfloat162 h0 = __float22bfloat162_rn(make_float2(v.x, v.y));
        __nv_bfloat162 h1 = __float22bfloat162_rn(make_float2(v.z, v.w));
        ((uint2*)xbr)[idx] = make_uint2(*(uint32_t*)&h0, *(uint32_t*)&h1);
    }

    if (tid < TT) {
        float s = 0.f;
        #pragma unroll
        for (int f = 0; f < FF; f++) s += xs[tid * FF + f];
        S[tid] = s;
    }
    __syncthreads();

    #pragma unroll
    for (int j = 0; j < 12; j++) {
        int idx = j * 128 + tid;
        int tp = idx >> 6, f = idx & 63;
        float acc = 0.f;
        #pragma unroll
        for (int t = 0; t < TT; t++)
            acc = fmaf(xs[t * FF + f], W2s[t * TT + tp], acc);
        outr[tp * FA + f] = 0.5f * xs[idx] + 0.25f * acc + 0.25f * S[tp] * RWs[f];
    }
    for (int idx = tid; idx < TT * (FA - FF); idx += 128) {
        int tp = idx / (FA - FF);
        int f  = FF + idx % (FA - FF);
        outr[tp * FA + f] = fmaxf(0.25f * S[tp] * RWs[f], 0.f);
    }
}

// ---------------------------------------------------------------------------
// GEMM + fused epilogue:
//   acc = adj @ x  (bf16 in, fp32 acc); out = relu(base + 0.125*sigA[i]*acc)
// CTA 128x128, K=512 in 8 stages of 64, 3-stage cp.async pipeline.
// 8 warps 2(m)x4(n), warp tile 64x32.
// ---------------------------------------------------------------------------
__global__ __launch_bounds__(256)
void gemm_kernel(float* __restrict__ out) {
    extern __shared__ char smem[];
    uint32_t sb = smem_u32(smem);

    int tid = threadIdx.x, l = tid & 31, wid = tid >> 5;
    int wm = wid & 1, wn = wid >> 1;
    int b = blockIdx.z, i0 = blockIdx.y * BM, c0 = blockIdx.x * BN;
    const __nv_bfloat16* Xb = g_xb + (size_t)b * NN * TF;

#define ISSUE_STAGE(s)                                                          \
    {                                                                           \
        int buf_ = (s) % STAGES;                                                \
        int k0_ = (s) * BK;                                                     \
        uint32_t ab_ = sb + buf_ * ASTGB;                                       \
        uint32_t bb_ = sb + STAGES * ASTGB + buf_ * BSTGB;                      \
        _Pragma("unroll")                                                       \
        for (int u = 0; u < 4; u++) {                                           \
            int id = u * 256 + tid;                                             \
            int ar = id >> 3, ac = id & 7;                                      \
            CP16(ab_ + ar * AROWB + ac * 16,                                    \
                 (const char*)(g_adjb + (size_t)(i0 + ar) * NN + k0_) + ac * 16); \
            int br = id >> 4, bc = id & 15;                                     \
            CP16(bb_ + br * BROWB + bc * 16,                                    \
                 (const char*)(Xb + (size_t)(k0_ + br) * TF + c0) + bc * 16);   \
        }                                                                       \
    }

    float acc[4][4][4];
    #pragma unroll
    for (int mt = 0; mt < 4; mt++)
        #pragma unroll
        for (int nt = 0; nt < 4; nt++)
            #pragma unroll
            for (int q = 0; q < 4; q++) acc[mt][nt][q] = 0.f;

    uint32_t a_off = (uint32_t)(wm * 64 + (l & 15)) * AROWB + (l >> 4) * 16;
    uint32_t b_off = (uint32_t)(l & 15) * BROWB + (wn * 32 + ((l >> 4) << 3)) * 2;

    ISSUE_STAGE(0); CP_COMMIT();
    ISSUE_STAGE(1); CP_COMMIT();

    for (int s = 0; s < NKS; s++) {
        int buf = s % STAGES;
        CP_WAIT1();
        __syncthreads();

        if (s + 2 < NKS) ISSUE_STAGE(s + 2);
        CP_COMMIT();   // always commit so wait_group 1 tracks stage s exactly

        uint32_t ab = sb + buf * ASTGB + a_off;
        uint32_t bb = sb + STAGES * ASTGB + buf * BSTGB + b_off;
        #pragma unroll
        for (int ks = 0; ks < 4; ks++) {
            uint32_t af[4][4], bf[2][4];
            #pragma unroll
            for (int mt = 0; mt < 4; mt++)
                ldsm4(af[mt], ab + mt * 16 * AROWB + ks * 32);
            #pragma unroll
            for (int n2 = 0; n2 < 2; n2++)
                ldsm4t(bf[n2], bb + ks * 16 * BROWB + n2 * 32);
            #pragma unroll
            for (int mt = 0; mt < 4; mt++)
                #pragma unroll
                for (int nt = 0; nt < 4; nt++)
                    mma16816(acc[mt][nt], af[mt], &bf[nt >> 1][(nt & 1) * 2]);
        }
        __syncthreads();
    }

    // fused epilogue: out = relu(base + 0.125*sigA[i]*acc)
    int rbase = i0 + wm * 64 + (l >> 2);
    int cbase = c0 + wn * 32 + (l & 3) * 2;
    #pragma unroll
    for (int mt = 0; mt < 4; mt++) {
        int i1 = rbase + mt * 16;
        float cf1 = 0.125f * g_sigA[i1];
        float cf2 = 0.125f * g_sigA[i1 + 8];
        size_t ro1 = ((size_t)(b * NN + i1)) * OUTROW;
        size_t ro2 = ro1 + (size_t)8 * OUTROW;
        #pragma unroll
        for (int nt = 0; nt < 4; nt++) {
            int c = cbase + nt * 8;
            int t = c >> 6, f = c & 63;
            size_t o = (size_t)t * FA + f;
            float2 b1 = *(float2*)&out[ro1 + o];
            float2 b2 = *(float2*)&out[ro2 + o];
            float2 r1 = make_float2(fmaxf(b1.x + cf1 * acc[mt][nt][0], 0.f),
                                    fmaxf(b1.y + cf1 * acc[mt][nt][1], 0.f));
            float2 r2 = make_float2(fmaxf(b2.x + cf2 * acc[mt][nt][2], 0.f),
                                    fmaxf(b2.y + cf2 * acc[mt][nt][3], 0.f));
            *(float2*)&out[ro1 + o] = r1;
            *(float2*)&out[ro2 + o] = r2;
        }
    }
}

extern "C" void kernel_launch(void* const* d_in, const int* in_sizes, int n_in,
                              void* d_out, int out_size) {
    const float* x     = (const float*)d_in[0];
    const float* adj   = (const float*)d_in[1];
    const float* alpha = (const float*)d_in[2];
    const float* w     = (const float*)d_in[3];
    const float* d     = (const float*)d_in[4];
    const float* w2    = (const float*)d_in[5];
    const float* d2    = (const float*)d_in[6];
    float* out = (float*)d_out;

    cudaFuncSetAttribute(gemm_kernel, cudaFuncAttributeMaxDynamicSharedMemorySize, GEMM_SMEM);

    prep_kernel<<<1, 256>>>(alpha, w, d, w2, d2);
    convert_adj_kernel<<<(NN * NN / 8) / 256, 256>>>(adj);
    basex_kernel<<<B_ * NN, 128>>>(x, out);
    dim3 grid(TF / BN, NN / BM, B_);
    gemm_kernel<<<grid, 256, GEMM_SMEM>>>(out);
}

// round 6
// speedup vs baseline: 1.0009x; 1.0009x over previous
#include <cuda_runtime.h>
#include <cuda_bf16.h>
#include <cstdint>

#define B_  32
#define NN  512
#define TT  24
#define FF  64
#define FA  74
#define TF  1536      // TT*FF
#define OUTROW 1776   // TT*FA

#define BM 128
#define BN 128
#define BK 32
#define NKS (NN / BK)  // 16
#define STAGES 4

#define AROWB 80        // A row bytes in smem (64 data + 16 pad)
#define BROWB 272       // B row bytes in smem (256 data + 16 pad)
#define ASTGB (BM * AROWB)            // 10240
#define BSTGB (BK * BROWB)            // 8704
#define GEMM_SMEM (STAGES * (ASTGB + BSTGB))   // 75776

__device__ float g_RW[FA];
__device__ float g_W2[TT * TT];
__device__ float g_sigA[NN];
__device__ __nv_bfloat16 g_xb[(size_t)B_ * NN * TF];
__device__ __nv_bfloat16 g_adjb[(size_t)NN * NN];

// ---------------------------------------------------------------------------
__device__ __forceinline__ uint32_t smem_u32(const void* p) {
    uint32_t a;
    asm("{ .reg .u64 t; cvta.to.shared.u64 t, %1; cvt.u32.u64 %0, t; }" : "=r"(a) : "l"(p));
    return a;
}
__device__ __forceinline__ void ldsm4(uint32_t* r, uint32_t addr) {
    asm volatile("ldmatrix.sync.aligned.m8n8.x4.shared.b16 {%0,%1,%2,%3}, [%4];"
                 : "=r"(r[0]), "=r"(r[1]), "=r"(r[2]), "=r"(r[3]) : "r"(addr));
}
__device__ __forceinline__ void ldsm4t(uint32_t* r, uint32_t addr) {
    asm volatile("ldmatrix.sync.aligned.m8n8.x4.trans.shared.b16 {%0,%1,%2,%3}, [%4];"
                 : "=r"(r[0]), "=r"(r[1]), "=r"(r[2]), "=r"(r[3]) : "r"(addr));
}
__device__ __forceinline__ void mma16816(float* c, const uint32_t* a, const uint32_t* b) {
    asm volatile(
        "mma.sync.aligned.m16n8k16.row.col.f32.bf16.bf16.f32 "
        "{%0,%1,%2,%3}, {%4,%5,%6,%7}, {%8,%9}, {%0,%1,%2,%3};"
        : "+f"(c[0]), "+f"(c[1]), "+f"(c[2]), "+f"(c[3])
        : "r"(a[0]), "r"(a[1]), "r"(a[2]), "r"(a[3]), "r"(b[0]), "r"(b[1]));
}
#define CP16(dst, src) \
    asm volatile("cp.async.cg.shared.global [%0], [%1], 16;" :: "r"(dst), "l"(src) : "memory")
#define CP_COMMIT() asm volatile("cp.async.commit_group;" ::: "memory")
#define CP_WAIT2()  asm volatile("cp.async.wait_group 2;" ::: "memory")

// ---------------------------------------------------------------------------
// Prep: RW, W2eff, sigmoid(alpha)
// ---------------------------------------------------------------------------
__global__ void prep_kernel(const float* __restrict__ alpha,
                            const float* __restrict__ w,
                            const float* __restrict__ d,
                            const float* __restrict__ w2,
                            const float* __restrict__ d2) {
    __shared__ float colsum[FA];
    __shared__ float dc[FA];
    int tid = threadIdx.x;  // 256

    for (int n = tid; n < NN; n += 256)
        g_sigA[n] = 1.0f / (1.0f + expf(-alpha[n]));

    if (tid < FA) {
        float s = 0.f;
        for (int n = 0; n < FA; n++) s += w[n * FA + tid];
        colsum[tid] = s;
        dc[tid] = fminf(fmaxf(d[tid], 0.f), 1.f);
    }
    __syncthreads();
    if (tid < FA) {
        float s = 0.f;
        for (int k = 0; k < FA; k++) s += w[tid * FA + k] * dc[k] * colsum[k];
        g_RW[tid] = s;
    }
    for (int idx = tid; idx < TT * TT; idx += 256) {
        int t = idx / TT, tp = idx % TT;
        float s = 0.f;
        for (int k = 0; k < TT; k++) {
            float dk = fminf(fmaxf(d2[k], 0.f), 1.f);
            s += w2[t * TT + k] * dk * w2[tp * TT + k];
        }
        g_W2[idx] = s;
    }
}

__global__ void convert_adj_kernel(const float* __restrict__ adj) {
    size_t i = (size_t)blockIdx.x * 256 + threadIdx.x;
    const float4* src = (const float4*)adj + i * 2;
    float4 a = src[0], b = src[1];
    __nv_bfloat162 h0 = __float22bfloat162_rn(make_float2(a.x, a.y));
    __nv_bfloat162 h1 = __float22bfloat162_rn(make_float2(a.z, a.w));
    __nv_bfloat162 h2 = __float22bfloat162_rn(make_float2(b.x, b.y));
    __nv_bfloat162 h3 = __float22bfloat162_rn(make_float2(b.z, b.w));
    ((uint4*)g_adjb)[i] = make_uint4(*(uint32_t*)&h0, *(uint32_t*)&h1,
                                     *(uint32_t*)&h2, *(uint32_t*)&h3);
}

// ---------------------------------------------------------------------------
// basex: per (b,n) row — convert x->bf16 (for GEMM) AND write base terms:
//   out[t,f<64]  = 0.5*x + 0.25*xw2 + 0.25*S*RW      (raw; GEMM epilogue relu's)
//   out[t,f>=64] = relu(0.25*S*RW[f])                 (final)
// ---------------------------------------------------------------------------
__global__ __launch_bounds__(128)
void basex_kernel(const float* __restrict__ x, float* __restrict__ out) {
    int row = blockIdx.x;                // b*NN + node
    const float* xr = x + (size_t)row * TF;
    float* outr = out + (size_t)row * OUTROW;
    __nv_bfloat16* xbr = g_xb + (size_t)row * TF;

    __shared__ float xs[TF];
    __shared__ float W2s[TT * TT];
    __shared__ float S[TT];
    __shared__ float RWs[FA];

    int tid = threadIdx.x;  // 128
    #pragma unroll
    for (int j = 0; j < 3; j++)
        ((float4*)xs)[j * 128 + tid] = ((const float4*)xr)[j * 128 + tid];
    for (int j = tid; j < TT * TT; j += 128) W2s[j] = g_W2[j];
    if (tid < FA) RWs[tid] = g_RW[tid];
    __syncthreads();

    // write bf16 copy for the GEMM
    #pragma unroll
    for (int j = 0; j < 3; j++) {
        int idx = j * 128 + tid;
        float4 v = ((const float4*)xs)[idx];
        __nv_bfloat162 h0 = __float22bfloat162_rn(make_float2(v.x, v.y));
        __nv_bfloat162 h1 = __float22bfloat162_rn(make_float2(v.z, v.w));
        ((uint2*)xbr)[idx] = make_uint2(*(uint32_t*)&h0, *(uint32_t*)&h1);
    }

    if (tid < TT) {
        float s = 0.f;
        #pragma unroll
        for (int f = 0; f < FF; f++) s += xs[tid * FF + f];
        S[tid] = s;
    }
    __syncthreads();

    #pragma unroll
    for (int j = 0; j < 12; j++) {
        int idx = j * 128 + tid;
        int tp = idx >> 6, f = idx & 63;
        float acc = 0.f;
        #pragma unroll
        for (int t = 0; t < TT; t++)
            acc = fmaf(xs[t * FF + f], W2s[t * TT + tp], acc);
        outr[tp * FA + f] = 0.5f * xs[idx] + 0.25f * acc + 0.25f * S[tp] * RWs[f];
    }
    for (int idx = tid; idx < TT * (FA - FF); idx += 128) {
        int tp = idx / (FA - FF);
        int f  = FF + idx % (FA - FF);
        outr[tp * FA + f] = fmaxf(0.25f * S[tp] * RWs[f], 0.f);
    }
}

// ---------------------------------------------------------------------------
// GEMM + fused epilogue (R4 mainloop config):
//   acc = adj @ x (bf16 in, fp32 acc); out = relu(base + 0.125*sigA[i]*acc)
// CTA 128x128, K=512 in 16 stages of 32, 4-stage cp.async pipeline.
// 8 warps 2(m)x4(n), warp tile 64x32.
// ---------------------------------------------------------------------------
__global__ __launch_bounds__(256)
void gemm_kernel(float* __restrict__ out) {
    extern __shared__ char smem[];
    uint32_t sb = smem_u32(smem);

    int tid = threadIdx.x, l = tid & 31, wid = tid >> 5;
    int wm = wid & 1, wn = wid >> 1;
    int b = blockIdx.z, i0 = blockIdx.y * BM, c0 = blockIdx.x * BN;
    const __nv_bfloat16* Xb = g_xb + (size_t)b * NN * TF;

#define ISSUE_STAGE(s)                                                          \
    {                                                                           \
        int buf_ = (s) & (STAGES - 1);                                          \
        int k0_ = (s) * BK;                                                     \
        uint32_t ab_ = sb + buf_ * ASTGB;                                       \
        uint32_t bb_ = sb + STAGES * ASTGB + buf_ * BSTGB;                      \
        _Pragma("unroll")                                                       \
        for (int u = 0; u < 2; u++) {                                           \
            int id = u * 256 + tid;                                             \
            int ar = id >> 2, ac = id & 3;                                      \
            CP16(ab_ + ar * AROWB + ac * 16,                                    \
                 (const char*)(g_adjb + (size_t)(i0 + ar) * NN + k0_) + ac * 16); \
            int br = id >> 4, bc = id & 15;                                     \
            CP16(bb_ + br * BROWB + bc * 16,                                    \
                 (const char*)(Xb + (size_t)(k0_ + br) * TF + c0) + bc * 16);   \
        }                                                                       \
    }

    float acc[4][4][4];
    #pragma unroll
    for (int mt = 0; mt < 4; mt++)
        #pragma unroll
        for (int nt = 0; nt < 4; nt++)
            #pragma unroll
            for (int q = 0; q < 4; q++) acc[mt][nt][q] = 0.f;

    uint32_t a_off = (uint32_t)(wm * 64 + (l & 15)) * AROWB + ((l >> 4) * 8) * 2;
    uint32_t b_off = (uint32_t)(l & 15) * BROWB + (wn * 32 + ((l >> 4) << 3)) * 2;

    ISSUE_STAGE(0); CP_COMMIT();
    ISSUE_STAGE(1); CP_COMMIT();
    ISSUE_STAGE(2); CP_COMMIT();

    for (int s = 0; s < NKS; s++) {
        int buf = s & (STAGES - 1);
        CP_WAIT2();
        __syncthreads();

        if (s + 3 < NKS) ISSUE_STAGE(s + 3);
        CP_COMMIT();   // always commit so wait_group 2 tracks stage s exactly

        uint32_t ab = sb + buf * ASTGB + a_off;
        uint32_t bb = sb + STAGES * ASTGB + buf * BSTGB + b_off;
        #pragma unroll
        for (int ks = 0; ks < 2; ks++) {
            uint32_t af[4][4], bf[2][4];
            #pragma unroll
            for (int mt = 0; mt < 4; mt++)
                ldsm4(af[mt], ab + mt * 16 * AROWB + ks * 32);
            #pragma unroll
            for (int n2 = 0; n2 < 2; n2++)
                ldsm4t(bf[n2], bb + ks * 16 * BROWB + n2 * 32);
            #pragma unroll
            for (int mt = 0; mt < 4; mt++)
                #pragma unroll
                for (int nt = 0; nt < 4; nt++)
                    mma16816(acc[mt][nt], af[mt], &bf[nt >> 1][(nt & 1) * 2]);
        }
        __syncthreads();
    }

    // fused epilogue: out = relu(base + 0.125*sigA[i]*acc)
    int rbase = i0 + wm * 64 + (l >> 2);
    int cbase = c0 + wn * 32 + (l & 3) * 2;
    #pragma unroll
    for (int mt = 0; mt < 4; mt++) {
        int i1 = rbase + mt * 16;
        float cf1 = 0.125f * g_sigA[i1];
        float cf2 = 0.125f * g_sigA[i1 + 8];
        size_t ro1 = ((size_t)(b * NN + i1)) * OUTROW;
        size_t ro2 = ro1 + (size_t)8 * OUTROW;
        #pragma unroll
        for (int nt = 0; nt < 4; nt++) {
            int c = cbase + nt * 8;
            int t = c >> 6, f = c & 63;
            size_t o = (size_t)t * FA + f;
            float2 b1 = *(float2*)&out[ro1 + o];
            float2 b2 = *(float2*)&out[ro2 + o];
            float2 r1 = make_float2(fmaxf(b1.x + cf1 * acc[mt][nt][0], 0.f),
                                    fmaxf(b1.y + cf1 * acc[mt][nt][1], 0.f));
            float2 r2 = make_float2(fmaxf(b2.x + cf2 * acc[mt][nt][2], 0.f),
                                    fmaxf(b2.y + cf2 * acc[mt][nt][3], 0.f));
            *(float2*)&out[ro1 + o] = r1;
            *(float2*)&out[ro2 + o] = r2;
        }
    }
}

extern "C" void kernel_launch(void* const* d_in, const int* in_sizes, int n_in,
                              void* d_out, int out_size) {
    const float* x     = (const float*)d_in[0];
    const float* adj   = (const float*)d_in[1];
    const float* alpha = (const float*)d_in[2];
    const float* w     = (const float*)d_in[3];
    const float* d     = (const float*)d_in[4];
    const float* w2    = (const float*)d_in[5];
    const float* d2    = (const float*)d_in[6];
    float* out = (float*)d_out;

    cudaFuncSetAttribute(gemm_kernel, cudaFuncAttributeMaxDynamicSharedMemorySize, GEMM_SMEM);

    prep_kernel<<<1, 256>>>(alpha, w, d, w2, d2);
    convert_adj_kernel<<<(NN * NN / 8) / 256, 256>>>(adj);
    basex_kernel<<<B_ * NN, 128>>>(x, out);
    dim3 grid(TF / BN, NN / BM, B_);
    gemm_kernel<<<grid, 256, GEMM_SMEM>>>(out);
}

// round 7
// speedup vs baseline: 1.1140x; 1.1129x over previous
#include <cuda_runtime.h>
#include <cuda_bf16.h>
#include <cstdint>

#define B_  32
#define NN  512
#define TT  24
#define FF  64
#define FA  74
#define TF  1536      // TT*FF
#define OUTROW 1776   // TT*FA

#define BM 128
#define BN 128
#define BK 32
#define NKS (NN / BK)  // 16
#define STAGES 4

#define AROWB 80        // A row bytes in smem (64 data + 16 pad)
#define BROWB 272       // B row bytes in smem (256 data + 16 pad)
#define ASTGB (BM * AROWB)            // 10240
#define BSTGB (BK * BROWB)            // 8704
#define GEMM_SMEM (STAGES * (ASTGB + BSTGB))   // 75776  (also >= 128*132*4+512)

__device__ float g_RW[FA];
__device__ float g_W2[TT * TT];
__device__ float g_sigA[NN];
__device__ __nv_bfloat16 g_xb[(size_t)B_ * NN * TF];
__device__ __nv_bfloat16 g_adjb[(size_t)NN * NN];

// ---------------------------------------------------------------------------
__device__ __forceinline__ uint32_t smem_u32(const void* p) {
    uint32_t a;
    asm("{ .reg .u64 t; cvta.to.shared.u64 t, %1; cvt.u32.u64 %0, t; }" : "=r"(a) : "l"(p));
    return a;
}
__device__ __forceinline__ void ldsm4(uint32_t* r, uint32_t addr) {
    asm volatile("ldmatrix.sync.aligned.m8n8.x4.shared.b16 {%0,%1,%2,%3}, [%4];"
                 : "=r"(r[0]), "=r"(r[1]), "=r"(r[2]), "=r"(r[3]) : "r"(addr));
}
__device__ __forceinline__ void ldsm4t(uint32_t* r, uint32_t addr) {
    asm volatile("ldmatrix.sync.aligned.m8n8.x4.trans.shared.b16 {%0,%1,%2,%3}, [%4];"
                 : "=r"(r[0]), "=r"(r[1]), "=r"(r[2]), "=r"(r[3]) : "r"(addr));
}
__device__ __forceinline__ void mma16816(float* c, const uint32_t* a, const uint32_t* b) {
    asm volatile(
        "mma.sync.aligned.m16n8k16.row.col.f32.bf16.bf16.f32 "
        "{%0,%1,%2,%3}, {%4,%5,%6,%7}, {%8,%9}, {%0,%1,%2,%3};"
        : "+f"(c[0]), "+f"(c[1]), "+f"(c[2]), "+f"(c[3])
        : "r"(a[0]), "r"(a[1]), "r"(a[2]), "r"(a[3]), "r"(b[0]), "r"(b[1]));
}
#define CP16(dst, src) \
    asm volatile("cp.async.cg.shared.global [%0], [%1], 16;" :: "r"(dst), "l"(src) : "memory")
#define CP_COMMIT() asm volatile("cp.async.commit_group;" ::: "memory")
#define CP_WAIT2()  asm volatile("cp.async.wait_group 2;" ::: "memory")

// ---------------------------------------------------------------------------
// Prep: RW, W2eff, sigmoid(alpha)
// ---------------------------------------------------------------------------
__global__ void prep_kernel(const float* __restrict__ alpha,
                            const float* __restrict__ w,
                            const float* __restrict__ d,
                            const float* __restrict__ w2,
                            const float* __restrict__ d2) {
    __shared__ float colsum[FA];
    __shared__ float dc[FA];
    int tid = threadIdx.x;  // 256

    for (int n = tid; n < NN; n += 256)
        g_sigA[n] = 1.0f / (1.0f + expf(-alpha[n]));

    if (tid < FA) {
        float s = 0.f;
        for (int n = 0; n < FA; n++) s += w[n * FA + tid];
        colsum[tid] = s;
        dc[tid] = fminf(fmaxf(d[tid], 0.f), 1.f);
    }
    __syncthreads();
    if (tid < FA) {
        float s = 0.f;
        for (int k = 0; k < FA; k++) s += w[tid * FA + k] * dc[k] * colsum[k];
        g_RW[tid] = s;
    }
    for (int idx = tid; idx < TT * TT; idx += 256) {
        int t = idx / TT, tp = idx % TT;
        float s = 0.f;
        for (int k = 0; k < TT; k++) {
            float dk = fminf(fmaxf(d2[k], 0.f), 1.f);
            s += w2[t * TT + k] * dk * w2[tp * TT + k];
        }
        g_W2[idx] = s;
    }
}

__global__ void convert_adj_kernel(const float* __restrict__ adj) {
    size_t i = (size_t)blockIdx.x * 256 + threadIdx.x;
    const float4* src = (const float4*)adj + i * 2;
    float4 a = src[0], b = src[1];
    __nv_bfloat162 h0 = __float22bfloat162_rn(make_float2(a.x, a.y));
    __nv_bfloat162 h1 = __float22bfloat162_rn(make_float2(a.z, a.w));
    __nv_bfloat162 h2 = __float22bfloat162_rn(make_float2(b.x, b.y));
    __nv_bfloat162 h3 = __float22bfloat162_rn(make_float2(b.z, b.w));
    ((uint4*)g_adjb)[i] = make_uint4(*(uint32_t*)&h0, *(uint32_t*)&h1,
                                     *(uint32_t*)&h2, *(uint32_t*)&h3);
}

// ---------------------------------------------------------------------------
// basex: per (b,n) row — convert x->bf16 AND write base terms.
// xw2 computed as register-blocked 24x64 mini-GEMM: thread = 3 tp x 4 f.
// ---------------------------------------------------------------------------
__global__ __launch_bounds__(128)
void basex_kernel(const float* __restrict__ x, float* __restrict__ out) {
    int row = blockIdx.x;                // b*NN + node
    const float* xr = x + (size_t)row * TF;
    float* outr = out + (size_t)row * OUTROW;
    __nv_bfloat16* xbr = g_xb + (size_t)row * TF;

    __shared__ float xs[TF];
    __shared__ float W2s[TT * TT];
    __shared__ float S[TT];
    __shared__ float RWs[FA];

    int tid = threadIdx.x;  // 128
    #pragma unroll
    for (int j = 0; j < 3; j++)
        ((float4*)xs)[j * 128 + tid] = ((const float4*)xr)[j * 128 + tid];
    for (int j = tid; j < TT * TT; j += 128) W2s[j] = g_W2[j];
    if (tid < FA) RWs[tid] = g_RW[tid];
    __syncthreads();

    // bf16 copy for the GEMM
    #pragma unroll
    for (int j = 0; j < 3; j++) {
        int idx = j * 128 + tid;
        float4 v = ((const float4*)xs)[idx];
        __nv_bfloat162 h0 = __float22bfloat162_rn(make_float2(v.x, v.y));
        __nv_bfloat162 h1 = __float22bfloat162_rn(make_float2(v.z, v.w));
        ((uint2*)xbr)[idx] = make_uint2(*(uint32_t*)&h0, *(uint32_t*)&h1);
    }

    if (tid < TT) {
        float s = 0.f;
        #pragma unroll
        for (int f = 0; f < FF; f++) s += xs[tid * FF + f];
        S[tid] = s;
    }
    __syncthreads();

    // xw2 mini-GEMM: ty in [0,8) -> tp {ty, ty+8, ty+16}; tx in [0,16) -> f [4tx,4tx+4)
    int ty = tid >> 4, tx = tid & 15;
    float acc[3][4];
    #pragma unroll
    for (int r3 = 0; r3 < 3; r3++)
        #pragma unroll
        for (int q = 0; q < 4; q++) acc[r3][q] = 0.f;

    #pragma unroll
    for (int t = 0; t < TT; t++) {
        float4 xv = *(const float4*)&xs[t * FF + tx * 4];
        float w0 = W2s[t * TT + ty];
        float w1 = W2s[t * TT + ty + 8];
        float w2v = W2s[t * TT + ty + 16];
        acc[0][0] = fmaf(w0, xv.x, acc[0][0]); acc[0][1] = fmaf(w0, xv.y, acc[0][1]);
        acc[0][2] = fmaf(w0, xv.z, acc[0][2]); acc[0][3] = fmaf(w0, xv.w, acc[0][3]);
        acc[1][0] = fmaf(w1, xv.x, acc[1][0]); acc[1][1] = fmaf(w1, xv.y, acc[1][1]);
        acc[1][2] = fmaf(w1, xv.z, acc[1][2]); acc[1][3] = fmaf(w1, xv.w, acc[1][3]);
        acc[2][0] = fmaf(w2v, xv.x, acc[2][0]); acc[2][1] = fmaf(w2v, xv.y, acc[2][1]);
        acc[2][2] = fmaf(w2v, xv.z, acc[2][2]); acc[2][3] = fmaf(w2v, xv.w, acc[2][3]);
    }

    #pragma unroll
    for (int r3 = 0; r3 < 3; r3++) {
        int tp = ty + r3 * 8;
        float sr = 0.25f * S[tp];
        #pragma unroll
        for (int q = 0; q < 4; q += 2) {
            int f = tx * 4 + q;
            float2 o;
            o.x = 0.5f * xs[tp * FF + f]     + 0.25f * acc[r3][q]     + sr * RWs[f];
            o.y = 0.5f * xs[tp * FF + f + 1] + 0.25f * acc[r3][q + 1] + sr * RWs[f + 1];
            *(float2*)&outr[tp * FA + f] = o;
        }
    }
    for (int idx = tid; idx < TT * (FA - FF); idx += 128) {
        int tp = idx / (FA - FF);
        int f  = FF + idx % (FA - FF);
        outr[tp * FA + f] = fmaxf(0.25f * S[tp] * RWs[f], 0.f);
    }
}

// ---------------------------------------------------------------------------
// GEMM + staged coalesced epilogue:
//   acc = adj @ x (bf16 in, fp32 acc); out = relu(base + 0.125*sigA[i]*acc)
// Mainloop: CTA 128x128, 16 stages of K=32, 4-stage cp.async (R4 config).
// Epilogue: fragments -> smem tile (stride 132) -> coalesced float2 RMW of out.
// ---------------------------------------------------------------------------
__global__ __launch_bounds__(256)
void gemm_kernel(float* __restrict__ out) {
    extern __shared__ char smem[];
    uint32_t sb = smem_u32(smem);

    int tid = threadIdx.x, l = tid & 31, wid = tid >> 5;
    int wm = wid & 1, wn = wid >> 1;
    int b = blockIdx.z, i0 = blockIdx.y * BM, c0 = blockIdx.x * BN;
    const __nv_bfloat16* Xb = g_xb + (size_t)b * NN * TF;

#define ISSUE_STAGE(s)                                                          \
    {                                                                           \
        int buf_ = (s) & (STAGES - 1);                                          \
        int k0_ = (s) * BK;                                                     \
        uint32_t ab_ = sb + buf_ * ASTGB;                                       \
        uint32_t bb_ = sb + STAGES * ASTGB + buf_ * BSTGB;                      \
        _Pragma("unroll")                                                       \
        for (int u = 0; u < 2; u++) {                                           \
            int id = u * 256 + tid;                                             \
            int ar = id >> 2, ac = id & 3;                                      \
            CP16(ab_ + ar * AROWB + ac * 16,                                    \
                 (const char*)(g_adjb + (size_t)(i0 + ar) * NN + k0_) + ac * 16); \
            int br = id >> 4, bc = id & 15;                                     \
            CP16(bb_ + br * BROWB + bc * 16,                                    \
                 (const char*)(Xb + (size_t)(k0_ + br) * TF + c0) + bc * 16);   \
        }                                                                       \
    }

    float acc[4][4][4];
    #pragma unroll
    for (int mt = 0; mt < 4; mt++)
        #pragma unroll
        for (int nt = 0; nt < 4; nt++)
            #pragma unroll
            for (int q = 0; q < 4; q++) acc[mt][nt][q] = 0.f;

    uint32_t a_off = (uint32_t)(wm * 64 + (l & 15)) * AROWB + ((l >> 4) * 8) * 2;
    uint32_t b_off = (uint32_t)(l & 15) * BROWB + (wn * 32 + ((l >> 4) << 3)) * 2;

    ISSUE_STAGE(0); CP_COMMIT();
    ISSUE_STAGE(1); CP_COMMIT();
    ISSUE_STAGE(2); CP_COMMIT();

    for (int s = 0; s < NKS; s++) {
        int buf = s & (STAGES - 1);
        CP_WAIT2();
        __syncthreads();

        if (s + 3 < NKS) ISSUE_STAGE(s + 3);
        CP_COMMIT();   // always commit so wait_group 2 tracks stage s exactly

        uint32_t ab = sb + buf * ASTGB + a_off;
        uint32_t bb = sb + STAGES * ASTGB + buf * BSTGB + b_off;
        #pragma unroll
        for (int ks = 0; ks < 2; ks++) {
            uint32_t af[4][4], bf[2][4];
            #pragma unroll
            for (int mt = 0; mt < 4; mt++)
                ldsm4(af[mt], ab + mt * 16 * AROWB + ks * 32);
            #pragma unroll
            for (int n2 = 0; n2 < 2; n2++)
                ldsm4t(bf[n2], bb + ks * 16 * BROWB + n2 * 32);
            #pragma unroll
            for (int mt = 0; mt < 4; mt++)
                #pragma unroll
                for (int nt = 0; nt < 4; nt++)
                    mma16816(acc[mt][nt], af[mt], &bf[nt >> 1][(nt & 1) * 2]);
        }
        __syncthreads();
    }

    // ---- staged epilogue ----
    float* tile = (float*)smem;                       // [128][132]
    float* sigs = (float*)(smem + 128 * 132 * 4);     // [128]
    #pragma unroll
    for (int mt = 0; mt < 4; mt++) {
        int lr = wm * 64 + mt * 16 + (l >> 2);
        #pragma unroll
        for (int nt = 0; nt < 4; nt++) {
            int lc = wn * 32 + nt * 8 + (l & 3) * 2;
            *(float2*)&tile[lr * 132 + lc]       = make_float2(acc[mt][nt][0], acc[mt][nt][1]);
            *(float2*)&tile[(lr + 8) * 132 + lc] = make_float2(acc[mt][nt][2], acc[mt][nt][3]);
        }
    }
    if (tid < 128) sigs[tid] = 0.125f * g_sigA[i0 + tid];
    __syncthreads();

    int t0 = c0 >> 6;
    #pragma unroll 4
    for (int it = 0; it < 32; it++) {
        int idx = it * 256 + tid;      // [0, 8192)
        int r = idx >> 6, h = idx & 63;
        int col = h << 1;
        int t = t0 + (col >> 6);
        int f = col & 63;
        size_t o = ((size_t)(b * NN + i0 + r)) * OUTROW + t * FA + f;
        float2 bv = *(float2*)&out[o];
        float2 tv = *(float2*)&tile[r * 132 + col];
        float cf = sigs[r];
        float2 rv = make_float2(fmaxf(bv.x + cf * tv.x, 0.f),
                                fmaxf(bv.y + cf * tv.y, 0.f));
        *(float2*)&out[o] = rv;
    }
}

extern "C" void kernel_launch(void* const* d_in, const int* in_sizes, int n_in,
                              void* d_out, int out_size) {
    const float* x     = (const float*)d_in[0];
    const float* adj   = (const float*)d_in[1];
    const float* alpha = (const float*)d_in[2];
    const float* w     = (const float*)d_in[3];
    const float* d     = (const float*)d_in[4];
    const float* w2    = (const float*)d_in[5];
    const float* d2    = (const float*)d_in[6];
    float* out = (float*)d_out;

    cudaFuncSetAttribute(gemm_kernel, cudaFuncAttributeMaxDynamicSharedMemorySize, GEMM_SMEM);

    prep_kernel<<<1, 256>>>(alpha, w, d, w2, d2);
    convert_adj_kernel<<<(NN * NN / 8) / 256, 256>>>(adj);
    basex_kernel<<<B_ * NN, 128>>>(x, out);
    dim3 grid(TF / BN, NN / BM, B_);
    gemm_kernel<<<grid, 256, GEMM_SMEM>>>(out);
}

// round 8
// speedup vs baseline: 1.3453x; 1.2077x over previous
#include <cuda_runtime.h>
#include <cuda_bf16.h>
#include <cstdint>

#define B_  32
#define NN  512
#define TT  24
#define FF  64
#define FA  74
#define TF  1536      // TT*FF
#define OUTROW 1776   // TT*FA

#define BM 128
#define BN 128
#define BK 32
#define NKS (NN / BK)  // 16
#define STAGES 4

#define AROWB 80        // A row bytes in smem (64 data + 16 pad)
#define BROWB 272       // B row bytes in smem (256 data + 16 pad)
#define ASTGB (BM * AROWB)            // 10240
#define BSTGB (BK * BROWB)            // 8704
#define GEMM_SMEM (STAGES * (ASTGB + BSTGB))   // 75776

__device__ float g_RW[FA];
__device__ float g_W2[TT * TT];
__device__ float g_sigA[NN];
__device__ __nv_bfloat16 g_y[(size_t)B_ * NN * TF];
__device__ __nv_bfloat16 g_xb[(size_t)B_ * NN * TF];
__device__ __nv_bfloat16 g_adjb[(size_t)NN * NN];

// ---------------------------------------------------------------------------
__device__ __forceinline__ uint32_t smem_u32(const void* p) {
    uint32_t a;
    asm("{ .reg .u64 t; cvta.to.shared.u64 t, %1; cvt.u32.u64 %0, t; }" : "=r"(a) : "l"(p));
    return a;
}
__device__ __forceinline__ void ldsm4(uint32_t* r, uint32_t addr) {
    asm volatile("ldmatrix.sync.aligned.m8n8.x4.shared.b16 {%0,%1,%2,%3}, [%4];"
                 : "=r"(r[0]), "=r"(r[1]), "=r"(r[2]), "=r"(r[3]) : "r"(addr));
}
__device__ __forceinline__ void ldsm4t(uint32_t* r, uint32_t addr) {
    asm volatile("ldmatrix.sync.aligned.m8n8.x4.trans.shared.b16 {%0,%1,%2,%3}, [%4];"
                 : "=r"(r[0]), "=r"(r[1]), "=r"(r[2]), "=r"(r[3]) : "r"(addr));
}
__device__ __forceinline__ void mma16816(float* c, const uint32_t* a, const uint32_t* b) {
    asm volatile(
        "mma.sync.aligned.m16n8k16.row.col.f32.bf16.bf16.f32 "
        "{%0,%1,%2,%3}, {%4,%5,%6,%7}, {%8,%9}, {%0,%1,%2,%3};"
        : "+f"(c[0]), "+f"(c[1]), "+f"(c[2]), "+f"(c[3])
        : "r"(a[0]), "r"(a[1]), "r"(a[2]), "r"(a[3]), "r"(b[0]), "r"(b[1]));
}
#define CP16(dst, src) \
    asm volatile("cp.async.cg.shared.global [%0], [%1], 16;" :: "r"(dst), "l"(src) : "memory")
#define CP_COMMIT() asm volatile("cp.async.commit_group;" ::: "memory")
#define CP_WAIT2()  asm volatile("cp.async.wait_group 2;" ::: "memory")

// ---------------------------------------------------------------------------
// Prep: RW, W2eff, sigmoid(alpha)
// ---------------------------------------------------------------------------
__global__ void prep_kernel(const float* __restrict__ alpha,
                            const float* __restrict__ w,
                            const float* __restrict__ d,
                            const float* __restrict__ w2,
                            const float* __restrict__ d2) {
    __shared__ float colsum[FA];
    __shared__ float dc[FA];
    int tid = threadIdx.x;  // 256

    for (int n = tid; n < NN; n += 256)
        g_sigA[n] = 1.0f / (1.0f + expf(-alpha[n]));

    if (tid < FA) {
        float s = 0.f;
        for (int n = 0; n < FA; n++) s += w[n * FA + tid];
        colsum[tid] = s;
        dc[tid] = fminf(fmaxf(d[tid], 0.f), 1.f);
    }
    __syncthreads();
    if (tid < FA) {
        float s = 0.f;
        for (int k = 0; k < FA; k++) s += w[tid * FA + k] * dc[k] * colsum[k];
        g_RW[tid] = s;
    }
    for (int idx = tid; idx < TT * TT; idx += 256) {
        int t = idx / TT, tp = idx % TT;
        float s = 0.f;
        for (int k = 0; k < TT; k++) {
            float dk = fminf(fmaxf(d2[k], 0.f), 1.f);
            s += w2[t * TT + k] * dk * w2[tp * TT + k];
        }
        g_W2[idx] = s;
    }
}

__global__ void convert_x_kernel(const float* __restrict__ x) {
    size_t i = (size_t)blockIdx.x * 256 + threadIdx.x;   // one per 8 floats
    const float4* src = (const float4*)x + i * 2;
    float4 a = src[0], b = src[1];
    __nv_bfloat162 h0 = __float22bfloat162_rn(make_float2(a.x, a.y));
    __nv_bfloat162 h1 = __float22bfloat162_rn(make_float2(a.z, a.w));
    __nv_bfloat162 h2 = __float22bfloat162_rn(make_float2(b.x, b.y));
    __nv_bfloat162 h3 = __float22bfloat162_rn(make_float2(b.z, b.w));
    ((uint4*)g_xb)[i] = make_uint4(*(uint32_t*)&h0, *(uint32_t*)&h1,
                                   *(uint32_t*)&h2, *(uint32_t*)&h3);
}
__global__ void convert_adj_kernel(const float* __restrict__ adj) {
    size_t i = (size_t)blockIdx.x * 256 + threadIdx.x;
    const float4* src = (const float4*)adj + i * 2;
    float4 a = src[0], b = src[1];
    __nv_bfloat162 h0 = __float22bfloat162_rn(make_float2(a.x, a.y));
    __nv_bfloat162 h1 = __float22bfloat162_rn(make_float2(a.z, a.w));
    __nv_bfloat162 h2 = __float22bfloat162_rn(make_float2(b.x, b.y));
    __nv_bfloat162 h3 = __float22bfloat162_rn(make_float2(b.z, b.w));
    ((uint4*)g_adjb)[i] = make_uint4(*(uint32_t*)&h0, *(uint32_t*)&h1,
                                     *(uint32_t*)&h2, *(uint32_t*)&h3);
}

// ---------------------------------------------------------------------------
// GEMM (R4 config): y[b,i,c] = sum_k adj[i,k]*x[b,k,c]  (bf16 in, fp32 acc,
// bf16 out to g_y). CTA 128x128, 16 K-stages of 32, 4-stage cp.async.
// ---------------------------------------------------------------------------
__global__ __launch_bounds__(256)
void gemm_kernel() {
    extern __shared__ char smem[];
    uint32_t sb = smem_u32(smem);

    int tid = threadIdx.x, l = tid & 31, wid = tid >> 5;
    int wm = wid & 1, wn = wid >> 1;
    int b = blockIdx.z, i0 = blockIdx.y * BM, c0 = blockIdx.x * BN;
    const __nv_bfloat16* Xb = g_xb + (size_t)b * NN * TF;

#define ISSUE_STAGE(s)                                                          \
    {                                                                           \
        int buf_ = (s) & (STAGES - 1);                                          \
        int k0_ = (s) * BK;                                                     \
        uint32_t ab_ = sb + buf_ * ASTGB;                                       \
        uint32_t bb_ = sb + STAGES * ASTGB + buf_ * BSTGB;                      \
        _Pragma("unroll")                                                       \
        for (int u = 0; u < 2; u++) {                                           \
            int id = u * 256 + tid;                                             \
            int ar = id >> 2, ac = id & 3;                                      \
            CP16(ab_ + ar * AROWB + ac * 16,                                    \
                 (const char*)(g_adjb + (size_t)(i0 + ar) * NN + k0_) + ac * 16); \
            int br = id >> 4, bc = id & 15;                                     \
            CP16(bb_ + br * BROWB + bc * 16,                                    \
                 (const char*)(Xb + (size_t)(k0_ + br) * TF + c0) + bc * 16);   \
        }                                                                       \
    }

    float acc[4][4][4];
    #pragma unroll
    for (int mt = 0; mt < 4; mt++)
        #pragma unroll
        for (int nt = 0; nt < 4; nt++)
            #pragma unroll
            for (int q = 0; q < 4; q++) acc[mt][nt][q] = 0.f;

    uint32_t a_off = (uint32_t)(wm * 64 + (l & 15)) * AROWB + ((l >> 4) * 8) * 2;
    uint32_t b_off = (uint32_t)(l & 15) * BROWB + (wn * 32 + ((l >> 4) << 3)) * 2;

    ISSUE_STAGE(0); CP_COMMIT();
    ISSUE_STAGE(1); CP_COMMIT();
    ISSUE_STAGE(2); CP_COMMIT();

    for (int s = 0; s < NKS; s++) {
        int buf = s & (STAGES - 1);
        CP_WAIT2();
        __syncthreads();

        if (s + 3 < NKS) ISSUE_STAGE(s + 3);
        CP_COMMIT();   // always commit so wait_group 2 tracks stage s exactly

        uint32_t ab = sb + buf * ASTGB + a_off;
        uint32_t bb = sb + STAGES * ASTGB + buf * BSTGB + b_off;
        #pragma unroll
        for (int ks = 0; ks < 2; ks++) {
            uint32_t af[4][4], bf[2][4];
            #pragma unroll
            for (int mt = 0; mt < 4; mt++)
                ldsm4(af[mt], ab + mt * 16 * AROWB + ks * 32);
            #pragma unroll
            for (int n2 = 0; n2 < 2; n2++)
                ldsm4t(bf[n2], bb + ks * 16 * BROWB + n2 * 32);
            #pragma unroll
            for (int mt = 0; mt < 4; mt++)
                #pragma unroll
                for (int nt = 0; nt < 4; nt++)
                    mma16816(acc[mt][nt], af[mt], &bf[nt >> 1][(nt & 1) * 2]);
        }
        __syncthreads();
    }

    // epilogue: fragments -> bf16 y
    int rbase = i0 + wm * 64 + (l >> 2);
    int cbase = c0 + wn * 32 + (l & 3) * 2;
    #pragma unroll
    for (int mt = 0; mt < 4; mt++) {
        #pragma unroll
        for (int nt = 0; nt < 4; nt++) {
            int i = rbase + mt * 16;
            int c = cbase + nt * 8;
            __nv_bfloat162 h0 = __float22bfloat162_rn(make_float2(acc[mt][nt][0], acc[mt][nt][1]));
            __nv_bfloat162 h1 = __float22bfloat162_rn(make_float2(acc[mt][nt][2], acc[mt][nt][3]));
            *(__nv_bfloat162*)&g_y[((size_t)b * NN + i) * TF + c] = h0;
            *(__nv_bfloat162*)&g_y[((size_t)b * NN + i + 8) * TF + c] = h1;
        }
    }
}

// ---------------------------------------------------------------------------
// Combine: 2 rows per block, 256 threads.
//   out = relu(0.5*x + 0.25*xw2 + 0.25*S*RW + 0.125*sigA*y), plus f>=64 strip.
// xw2: register-blocked 24x64 mini-GEMM per row half (ty 8 x tx 16, acc[3][4]).
// ---------------------------------------------------------------------------
__global__ __launch_bounds__(256)
void combine_kernel(const float* __restrict__ x, float* __restrict__ out) {
    int row0 = blockIdx.x * 2;           // b*NN + node, 2 consecutive rows
    int tid = threadIdx.x;
    int ri = tid >> 7, sub = tid & 127;
    int row = row0 + ri;
    const float* xr = x + (size_t)row * TF;
    const __nv_bfloat16* yr = g_y + (size_t)row * TF;
    float* outr = out + (size_t)row * OUTROW;

    __shared__ float xs[2][TF];
    __shared__ float W2s[TT * TT];
    __shared__ float S[2][TT];
    __shared__ float RWs[FA];

    #pragma unroll
    for (int j = 0; j < 3; j++)
        ((float4*)xs[ri])[j * 128 + sub] = ((const float4*)xr)[j * 128 + sub];
    for (int j = tid; j < TT * TT; j += 256) W2s[j] = g_W2[j];
    if (tid < FA) RWs[tid] = g_RW[tid];
    __syncthreads();

    if (tid < 48) {
        int r = tid >> 4 >= 2 ? 1 : (tid / 24);   // r = tid/24
        int t = tid - (tid / 24) * 24;
        r = tid / 24;
        float s = 0.f;
        #pragma unroll
        for (int f = 0; f < FF; f++) s += xs[r][t * FF + f];
        S[r][t] = s;
    }
    __syncthreads();

    // xw2 mini-GEMM: within row half, ty in [0,8) -> tp {ty,ty+8,ty+16}; tx -> f 4tx..
    int ty = sub >> 4, tx = sub & 15;
    float acc[3][4];
    #pragma unroll
    for (int r3 = 0; r3 < 3; r3++)
        #pragma unroll
        for (int q = 0; q < 4; q++) acc[r3][q] = 0.f;

    #pragma unroll
    for (int t = 0; t < TT; t++) {
        float4 xv = *(const float4*)&xs[ri][t * FF + tx * 4];
        float w0 = W2s[t * TT + ty];
        float w1 = W2s[t * TT + ty + 8];
        float w2v = W2s[t * TT + ty + 16];
        acc[0][0] = fmaf(w0, xv.x, acc[0][0]); acc[0][1] = fmaf(w0, xv.y, acc[0][1]);
        acc[0][2] = fmaf(w0, xv.z, acc[0][2]); acc[0][3] = fmaf(w0, xv.w, acc[0][3]);
        acc[1][0] = fmaf(w1, xv.x, acc[1][0]); acc[1][1] = fmaf(w1, xv.y, acc[1][1]);
        acc[1][2] = fmaf(w1, xv.z, acc[1][2]); acc[1][3] = fmaf(w1, xv.w, acc[1][3]);
        acc[2][0] = fmaf(w2v, xv.x, acc[2][0]); acc[2][1] = fmaf(w2v, xv.y, acc[2][1]);
        acc[2][2] = fmaf(w2v, xv.z, acc[2][2]); acc[2][3] = fmaf(w2v, xv.w, acc[2][3]);
    }

    float coef = 0.125f * g_sigA[row & (NN - 1)];
    #pragma unroll
    for (int r3 = 0; r3 < 3; r3++) {
        int tp = ty + r3 * 8;
        float sr = 0.25f * S[ri][tp];
        int f = tx * 4;
        // y: 4 bf16 coalesced (8B per thread, contiguous across tx)
        uint2 ypk = *(const uint2*)&yr[tp * FF + f];
        __nv_bfloat162 yl = *(__nv_bfloat162*)&ypk.x;
        __nv_bfloat162 yh = *(__nv_bfloat162*)&ypk.y;
        float o0 = 0.5f * xs[ri][tp * FF + f]     + 0.25f * acc[r3][0] + sr * RWs[f]
                 + coef * __bfloat162float(yl.x);
        float o1 = 0.5f * xs[ri][tp * FF + f + 1] + 0.25f * acc[r3][1] + sr * RWs[f + 1]
                 + coef * __bfloat162float(yl.y);
        float o2 = 0.5f * xs[ri][tp * FF + f + 2] + 0.25f * acc[r3][2] + sr * RWs[f + 2]
                 + coef * __bfloat162float(yh.x);
        float o3 = 0.5f * xs[ri][tp * FF + f + 3] + 0.25f * acc[r3][3] + sr * RWs[f + 3]
                 + coef * __bfloat162float(yh.y);
        *(float2*)&outr[tp * FA + f]     = make_float2(fmaxf(o0, 0.f), fmaxf(o1, 0.f));
        *(float2*)&outr[tp * FA + f + 2] = make_float2(fmaxf(o2, 0.f), fmaxf(o3, 0.f));
    }
    // f >= 64 strip: 2 rows x 240 elems
    for (int idx = tid; idx < 2 * TT * (FA - FF); idx += 256) {
        int r = idx / (TT * (FA - FF));
        int e = idx - r * (TT * (FA - FF));
        int tp = e / (FA - FF);
        int f  = FF + e % (FA - FF);
        out[((size_t)(row0 + r)) * OUTROW + tp * FA + f] =
            fmaxf(0.25f * S[r][tp] * RWs[f], 0.f);
    }
}

extern "C" void kernel_launch(void* const* d_in, const int* in_sizes, int n_in,
                              void* d_out, int out_size) {
    const float* x     = (const float*)d_in[0];
    const float* adj   = (const float*)d_in[1];
    const float* alpha = (const float*)d_in[2];
    const float* w     = (const float*)d_in[3];
    const float* d     = (const float*)d_in[4];
    const float* w2    = (const float*)d_in[5];
    const float* d2    = (const float*)d_in[6];
    float* out = (float*)d_out;

    cudaFuncSetAttribute(gemm_kernel, cudaFuncAttributeMaxDynamicSharedMemorySize, GEMM_SMEM);

    prep_kernel<<<1, 256>>>(alpha, w, d, w2, d2);
    convert_adj_kernel<<<(NN * NN / 8) / 256, 256>>>(adj);
    convert_x_kernel<<<((size_t)B_ * NN * TF / 8) / 256, 256>>>(x);
    dim3 grid(TF / BN, NN / BM, B_);
    gemm_kernel<<<grid, 256, GEMM_SMEM>>>();
    combine_kernel<<<B_ * NN / 2, 256>>>(x, out);
}

// round 9
// speedup vs baseline: 1.4254x; 1.0595x over previous
#include <cuda_runtime.h>
#include <cuda_bf16.h>
#include <cstdint>

#define B_  32
#define NN  512
#define TT  24
#define FF  64
#define FA  74
#define TF  1536      // TT*FF
#define OUTROW 1776   // TT*FA

#define BM 128
#define BN 128
#define BK 32
#define NKS (NN / BK)  // 16
#define STAGES 4

#define AROWB 80        // A row bytes in smem (64 data + 16 pad)
#define BROWB 272       // B row bytes in smem (256 data + 16 pad)
#define ASTGB (BM * AROWB)            // 10240
#define BSTGB (BK * BROWB)            // 8704
#define GEMM_SMEM (STAGES * (ASTGB + BSTGB))   // 75776

__device__ float g_RW[FA];
__device__ float g_W2[TT * TT];
__device__ float g_sigA[NN];
__device__ __nv_bfloat16 g_y[(size_t)B_ * NN * TF];
__device__ __nv_bfloat16 g_xb[(size_t)B_ * NN * TF];
__device__ __nv_bfloat16 g_adjb[(size_t)NN * NN];

// ---------------------------------------------------------------------------
__device__ __forceinline__ uint32_t smem_u32(const void* p) {
    uint32_t a;
    asm("{ .reg .u64 t; cvta.to.shared.u64 t, %1; cvt.u32.u64 %0, t; }" : "=r"(a) : "l"(p));
    return a;
}
__device__ __forceinline__ void ldsm4(uint32_t* r, uint32_t addr) {
    asm volatile("ldmatrix.sync.aligned.m8n8.x4.shared.b16 {%0,%1,%2,%3}, [%4];"
                 : "=r"(r[0]), "=r"(r[1]), "=r"(r[2]), "=r"(r[3]) : "r"(addr));
}
__device__ __forceinline__ void ldsm4t(uint32_t* r, uint32_t addr) {
    asm volatile("ldmatrix.sync.aligned.m8n8.x4.trans.shared.b16 {%0,%1,%2,%3}, [%4];"
                 : "=r"(r[0]), "=r"(r[1]), "=r"(r[2]), "=r"(r[3]) : "r"(addr));
}
__device__ __forceinline__ void mma16816(float* c, const uint32_t* a, const uint32_t* b) {
    asm volatile(
        "mma.sync.aligned.m16n8k16.row.col.f32.bf16.bf16.f32 "
        "{%0,%1,%2,%3}, {%4,%5,%6,%7}, {%8,%9}, {%0,%1,%2,%3};"
        : "+f"(c[0]), "+f"(c[1]), "+f"(c[2]), "+f"(c[3])
        : "r"(a[0]), "r"(a[1]), "r"(a[2]), "r"(a[3]), "r"(b[0]), "r"(b[1]));
}
#define CP16(dst, src) \
    asm volatile("cp.async.cg.shared.global [%0], [%1], 16;" :: "r"(dst), "l"(src) : "memory")
#define CP_COMMIT() asm volatile("cp.async.commit_group;" ::: "memory")
#define CP_WAIT2()  asm volatile("cp.async.wait_group 2;" ::: "memory")

// ---------------------------------------------------------------------------
// Prep: RW, W2eff, sigmoid(alpha)
// ---------------------------------------------------------------------------
__global__ void prep_kernel(const float* __restrict__ alpha,
                            const float* __restrict__ w,
                            const float* __restrict__ d,
                            const float* __restrict__ w2,
                            const float* __restrict__ d2) {
    __shared__ float colsum[FA];
    __shared__ float dc[FA];
    int tid = threadIdx.x;  // 256

    for (int n = tid; n < NN; n += 256)
        g_sigA[n] = 1.0f / (1.0f + expf(-alpha[n]));

    if (tid < FA) {
        float s = 0.f;
        for (int n = 0; n < FA; n++) s += w[n * FA + tid];
        colsum[tid] = s;
        dc[tid] = fminf(fmaxf(d[tid], 0.f), 1.f);
    }
    __syncthreads();
    if (tid < FA) {
        float s = 0.f;
        for (int k = 0; k < FA; k++) s += w[tid * FA + k] * dc[k] * colsum[k];
        g_RW[tid] = s;
    }
    for (int idx = tid; idx < TT * TT; idx += 256) {
        int t = idx / TT, tp = idx % TT;
        float s = 0.f;
        for (int k = 0; k < TT; k++) {
            float dk = fminf(fmaxf(d2[k], 0.f), 1.f);
            s += w2[t * TT + k] * dk * w2[tp * TT + k];
        }
        g_W2[idx] = s;
    }
}

__global__ void convert_x_kernel(const float* __restrict__ x) {
    size_t i = (size_t)blockIdx.x * 256 + threadIdx.x;   // one per 8 floats
    const float4* src = (const float4*)x + i * 2;
    float4 a = src[0], b = src[1];
    __nv_bfloat162 h0 = __float22bfloat162_rn(make_float2(a.x, a.y));
    __nv_bfloat162 h1 = __float22bfloat162_rn(make_float2(a.z, a.w));
    __nv_bfloat162 h2 = __float22bfloat162_rn(make_float2(b.x, b.y));
    __nv_bfloat162 h3 = __float22bfloat162_rn(make_float2(b.z, b.w));
    ((uint4*)g_xb)[i] = make_uint4(*(uint32_t*)&h0, *(uint32_t*)&h1,
                                   *(uint32_t*)&h2, *(uint32_t*)&h3);
}
__global__ void convert_adj_kernel(const float* __restrict__ adj) {
    size_t i = (size_t)blockIdx.x * 256 + threadIdx.x;
    const float4* src = (const float4*)adj + i * 2;
    float4 a = src[0], b = src[1];
    __nv_bfloat162 h0 = __float22bfloat162_rn(make_float2(a.x, a.y));
    __nv_bfloat162 h1 = __float22bfloat162_rn(make_float2(a.z, a.w));
    __nv_bfloat162 h2 = __float22bfloat162_rn(make_float2(b.x, b.y));
    __nv_bfloat162 h3 = __float22bfloat162_rn(make_float2(b.z, b.w));
    ((uint4*)g_adjb)[i] = make_uint4(*(uint32_t*)&h0, *(uint32_t*)&h1,
                                     *(uint32_t*)&h2, *(uint32_t*)&h3);
}

// ---------------------------------------------------------------------------
// GEMM: y[b,i,c] = sum_k adj[i,k]*x[b,k,c]  (bf16 in, fp32 acc, bf16 out)
// CTA 128x128, 4 warps (128 thr), warp tile 64x64, 16 K-stages of 32,
// 4-stage cp.async; single barrier per stage.
// ---------------------------------------------------------------------------
__global__ __launch_bounds__(128, 2)
void gemm_kernel() {
    extern __shared__ char smem[];
    uint32_t sb = smem_u32(smem);

    int tid = threadIdx.x, l = tid & 31, wid = tid >> 5;
    int wm = wid & 1, wn = wid >> 1;
    int b = blockIdx.z, i0 = blockIdx.y * BM, c0 = blockIdx.x * BN;
    const __nv_bfloat16* Xb = g_xb + (size_t)b * NN * TF;

#define ISSUE_STAGE(s)                                                          \
    {                                                                           \
        int buf_ = (s) & (STAGES - 1);                                          \
        int k0_ = (s) * BK;                                                     \
        uint32_t ab_ = sb + buf_ * ASTGB;                                       \
        uint32_t bb_ = sb + STAGES * ASTGB + buf_ * BSTGB;                      \
        _Pragma("unroll")                                                       \
        for (int u = 0; u < 4; u++) {                                           \
            int id = u * 128 + tid;                                             \
            int ar = id >> 2, ac = id & 3;                                      \
            CP16(ab_ + ar * AROWB + ac * 16,                                    \
                 (const char*)(g_adjb + (size_t)(i0 + ar) * NN + k0_) + ac * 16); \
            int br = id >> 4, bc = id & 15;                                     \
            CP16(bb_ + br * BROWB + bc * 16,                                    \
                 (const char*)(Xb + (size_t)(k0_ + br) * TF + c0) + bc * 16);   \
        }                                                                       \
    }

    float acc[4][8][4];
    #pragma unroll
    for (int mt = 0; mt < 4; mt++)
        #pragma unroll
        for (int nt = 0; nt < 8; nt++)
            #pragma unroll
            for (int q = 0; q < 4; q++) acc[mt][nt][q] = 0.f;

    uint32_t a_off = (uint32_t)(wm * 64 + (l & 15)) * AROWB + ((l >> 4) * 8) * 2;
    uint32_t b_off = (uint32_t)(l & 15) * BROWB + (wn * 64 + ((l >> 4) << 3)) * 2;

    ISSUE_STAGE(0); CP_COMMIT();
    ISSUE_STAGE(1); CP_COMMIT();
    ISSUE_STAGE(2); CP_COMMIT();

    for (int s = 0; s < NKS; s++) {
        int buf = s & (STAGES - 1);
        CP_WAIT2();
        __syncthreads();

        if (s + 3 < NKS) ISSUE_STAGE(s + 3);
        CP_COMMIT();   // always commit so wait_group 2 tracks stage s exactly

        uint32_t ab = sb + buf * ASTGB + a_off;
        uint32_t bb = sb + STAGES * ASTGB + buf * BSTGB + b_off;
        #pragma unroll
        for (int ks = 0; ks < 2; ks++) {
            uint32_t af[4][4], bf[4][4];
            #pragma unroll
            for (int mt = 0; mt < 4; mt++)
                ldsm4(af[mt], ab + mt * 16 * AROWB + ks * 32);
            #pragma unroll
            for (int n2 = 0; n2 < 4; n2++)
                ldsm4t(bf[n2], bb + ks * 16 * BROWB + n2 * 32);
            #pragma unroll
            for (int mt = 0; mt < 4; mt++)
                #pragma unroll
                for (int nt = 0; nt < 8; nt++)
                    mma16816(acc[mt][nt], af[mt], &bf[nt >> 1][(nt & 1) * 2]);
        }
        // NOTE: no trailing barrier — next iteration's top barrier protects
        // buffer (s-1)&3 before ISSUE_STAGE(s+4) overwrites it.
    }

    // epilogue: fragments -> bf16 y
    int rbase = i0 + wm * 64 + (l >> 2);
    int cbase = c0 + wn * 64 + (l & 3) * 2;
    #pragma unroll
    for (int mt = 0; mt < 4; mt++) {
        #pragma unroll
        for (int nt = 0; nt < 8; nt++) {
            int i = rbase + mt * 16;
            int c = cbase + nt * 8;
            __nv_bfloat162 h0 = __float22bfloat162_rn(make_float2(acc[mt][nt][0], acc[mt][nt][1]));
            __nv_bfloat162 h1 = __float22bfloat162_rn(make_float2(acc[mt][nt][2], acc[mt][nt][3]));
            *(__nv_bfloat162*)&g_y[((size_t)b * NN + i) * TF + c] = h0;
            *(__nv_bfloat162*)&g_y[((size_t)b * NN + i + 8) * TF + c] = h1;
        }
    }
}

// ---------------------------------------------------------------------------
// Combine: 2 rows per block, 256 threads (R8 version).
// ---------------------------------------------------------------------------
__global__ __launch_bounds__(256)
void combine_kernel(const float* __restrict__ x, float* __restrict__ out) {
    int row0 = blockIdx.x * 2;           // b*NN + node, 2 consecutive rows
    int tid = threadIdx.x;
    int ri = tid >> 7, sub = tid & 127;
    int row = row0 + ri;
    const float* xr = x + (size_t)row * TF;
    const __nv_bfloat16* yr = g_y + (size_t)row * TF;
    float* outr = out + (size_t)row * OUTROW;

    __shared__ float xs[2][TF];
    __shared__ float W2s[TT * TT];
    __shared__ float S[2][TT];
    __shared__ float RWs[FA];

    #pragma unroll
    for (int j = 0; j < 3; j++)
        ((float4*)xs[ri])[j * 128 + sub] = ((const float4*)xr)[j * 128 + sub];
    for (int j = tid; j < TT * TT; j += 256) W2s[j] = g_W2[j];
    if (tid < FA) RWs[tid] = g_RW[tid];
    __syncthreads();

    if (tid < 48) {
        int r = tid / 24;
        int t = tid - r * 24;
        float s = 0.f;
        #pragma unroll
        for (int f = 0; f < FF; f++) s += xs[r][t * FF + f];
        S[r][t] = s;
    }
    __syncthreads();

    int ty = sub >> 4, tx = sub & 15;
    float acc[3][4];
    #pragma unroll
    for (int r3 = 0; r3 < 3; r3++)
        #pragma unroll
        for (int q = 0; q < 4; q++) acc[r3][q] = 0.f;

    #pragma unroll
    for (int t = 0; t < TT; t++) {
        float4 xv = *(const float4*)&xs[ri][t * FF + tx * 4];
        float w0 = W2s[t * TT + ty];
        float w1 = W2s[t * TT + ty + 8];
        float w2v = W2s[t * TT + ty + 16];
        acc[0][0] = fmaf(w0, xv.x, acc[0][0]); acc[0][1] = fmaf(w0, xv.y, acc[0][1]);
        acc[0][2] = fmaf(w0, xv.z, acc[0][2]); acc[0][3] = fmaf(w0, xv.w, acc[0][3]);
        acc[1][0] = fmaf(w1, xv.x, acc[1][0]); acc[1][1] = fmaf(w1, xv.y, acc[1][1]);
        acc[1][2] = fmaf(w1, xv.z, acc[1][2]); acc[1][3] = fmaf(w1, xv.w, acc[1][3]);
        acc[2][0] = fmaf(w2v, xv.x, acc[2][0]); acc[2][1] = fmaf(w2v, xv.y, acc[2][1]);
        acc[2][2] = fmaf(w2v, xv.z, acc[2][2]); acc[2][3] = fmaf(w2v, xv.w, acc[2][3]);
    }

    float coef = 0.125f * g_sigA[row & (NN - 1)];
    #pragma unroll
    for (int r3 = 0; r3 < 3; r3++) {
        int tp = ty + r3 * 8;
        float sr = 0.25f * S[ri][tp];
        int f = tx * 4;
        uint2 ypk = *(const uint2*)&yr[tp * FF + f];
        __nv_bfloat162 yl = *(__nv_bfloat162*)&ypk.x;
        __nv_bfloat162 yh = *(__nv_bfloat162*)&ypk.y;
        float o0 = 0.5f * xs[ri][tp * FF + f]     + 0.25f * acc[r3][0] + sr * RWs[f]
                 + coef * __bfloat162float(yl.x);
        float o1 = 0.5f * xs[ri][tp * FF + f + 1] + 0.25f * acc[r3][1] + sr * RWs[f + 1]
                 + coef * __bfloat162float(yl.y);
        float o2 = 0.5f * xs[ri][tp * FF + f + 2] + 0.25f * acc[r3][2] + sr * RWs[f + 2]
                 + coef * __bfloat162float(yh.x);
        float o3 = 0.5f * xs[ri][tp * FF + f + 3] + 0.25f * acc[r3][3] + sr * RWs[f + 3]
                 + coef * __bfloat162float(yh.y);
        *(float2*)&outr[tp * FA + f]     = make_float2(fmaxf(o0, 0.f), fmaxf(o1, 0.f));
        *(float2*)&outr[tp * FA + f + 2] = make_float2(fmaxf(o2, 0.f), fmaxf(o3, 0.f));
    }
    for (int idx = tid; idx < 2 * TT * (FA - FF); idx += 256) {
        int r = idx / (TT * (FA - FF));
        int e = idx - r * (TT * (FA - FF));
        int tp = e / (FA - FF);
        int f  = FF + e % (FA - FF);
        out[((size_t)(row0 + r)) * OUTROW + tp * FA + f] =
            fmaxf(0.25f * S[r][tp] * RWs[f], 0.f);
    }
}

extern "C" void kernel_launch(void* const* d_in, const int* in_sizes, int n_in,
                              void* d_out, int out_size) {
    const float* x     = (const float*)d_in[0];
    const float* adj   = (const float*)d_in[1];
    const float* alpha = (const float*)d_in[2];
    const float* w     = (const float*)d_in[3];
    const float* d     = (const float*)d_in[4];
    const float* w2    = (const float*)d_in[5];
    const float* d2    = (const float*)d_in[6];
    float* out = (float*)d_out;

    cudaFuncSetAttribute(gemm_kernel, cudaFuncAttributeMaxDynamicSharedMemorySize, GEMM_SMEM);

    prep_kernel<<<1, 256>>>(alpha, w, d, w2, d2);
    convert_adj_kernel<<<(NN * NN / 8) / 256, 256>>>(adj);
    convert_x_kernel<<<((size_t)B_ * NN * TF / 8) / 256, 256>>>(x);
    dim3 grid(TF / BN, NN / BM, B_);
    gemm_kernel<<<grid, 128, GEMM_SMEM>>>();
    combine_kernel<<<B_ * NN / 2, 256>>>(x, out);
}

// round 10
// speedup vs baseline: 1.5308x; 1.0740x over previous
#include <cuda_runtime.h>
#include <cuda_bf16.h>
#include <cstdint>

#define B_  32
#define NN  512
#define TT  24
#define FF  64
#define FA  74
#define TF  1536      // TT*FF
#define OUTROW 1776   // TT*FA

#define BM 128
#define BN 128
#define BK 32
#define NKS (NN / BK)  // 16
#define STAGES 4

#define AROWB 80        // A row bytes in smem (64 data + 16 pad)
#define BROWB 272       // B row bytes in smem (256 data + 16 pad)
#define ASTGB (BM * AROWB)            // 10240
#define BSTGB (BK * BROWB)            // 8704
#define GEMM_SMEM (STAGES * (ASTGB + BSTGB))   // 75776

// pre_kernel block ranges
#define XBLKS ((B_ * NN * TF / 8) / 256)   // 12288
#define ADJBLKS ((NN * NN / 8) / 256)      // 128

__device__ float g_RW[FA];
__device__ float g_W2[TT * TT];
__device__ __nv_bfloat16 g_y[(size_t)B_ * NN * TF];
__device__ __nv_bfloat16 g_xb[(size_t)B_ * NN * TF];
__device__ __nv_bfloat16 g_adjb[(size_t)NN * NN];

// ---------------------------------------------------------------------------
__device__ __forceinline__ uint32_t smem_u32(const void* p) {
    uint32_t a;
    asm("{ .reg .u64 t; cvta.to.shared.u64 t, %1; cvt.u32.u64 %0, t; }" : "=r"(a) : "l"(p));
    return a;
}
__device__ __forceinline__ void ldsm4(uint32_t* r, uint32_t addr) {
    asm volatile("ldmatrix.sync.aligned.m8n8.x4.shared.b16 {%0,%1,%2,%3}, [%4];"
                 : "=r"(r[0]), "=r"(r[1]), "=r"(r[2]), "=r"(r[3]) : "r"(addr));
}
__device__ __forceinline__ void ldsm4t(uint32_t* r, uint32_t addr) {
    asm volatile("ldmatrix.sync.aligned.m8n8.x4.trans.shared.b16 {%0,%1,%2,%3}, [%4];"
                 : "=r"(r[0]), "=r"(r[1]), "=r"(r[2]), "=r"(r[3]) : "r"(addr));
}
__device__ __forceinline__ void mma16816(float* c, const uint32_t* a, const uint32_t* b) {
    asm volatile(
        "mma.sync.aligned.m16n8k16.row.col.f32.bf16.bf16.f32 "
        "{%0,%1,%2,%3}, {%4,%5,%6,%7}, {%8,%9}, {%0,%1,%2,%3};"
        : "+f"(c[0]), "+f"(c[1]), "+f"(c[2]), "+f"(c[3])
        : "r"(a[0]), "r"(a[1]), "r"(a[2]), "r"(a[3]), "r"(b[0]), "r"(b[1]));
}
#define CP16(dst, src) \
    asm volatile("cp.async.cg.shared.global [%0], [%1], 16;" :: "r"(dst), "l"(src) : "memory")
#define CP_COMMIT() asm volatile("cp.async.commit_group;" ::: "memory")
#define CP_WAIT2()  asm volatile("cp.async.wait_group 2;" ::: "memory")

// ---------------------------------------------------------------------------
// pre_kernel: fused independent pre-work, branch on blockIdx.x.
//   [0, XBLKS)                 : x fp32 -> bf16 g_xb
//   [XBLKS, XBLKS+ADJBLKS)     : adj -> bf16 g_adjb scaled by 0.125*sigmoid(alpha[i])
//   [XBLKS+ADJBLKS]            : RW + W2eff
// ---------------------------------------------------------------------------
__global__ __launch_bounds__(256)
void pre_kernel(const float* __restrict__ x, const float* __restrict__ adj,
                const float* __restrict__ alpha,
                const float* __restrict__ w, const float* __restrict__ d,
                const float* __restrict__ w2, const float* __restrict__ d2) {
    int bid = blockIdx.x;
    int tid = threadIdx.x;

    if (bid < XBLKS) {
        size_t i = (size_t)bid * 256 + tid;   // one per 8 floats
        const float4* src = (const float4*)x + i * 2;
        float4 a = src[0], b = src[1];
        __nv_bfloat162 h0 = __float22bfloat162_rn(make_float2(a.x, a.y));
        __nv_bfloat162 h1 = __float22bfloat162_rn(make_float2(a.z, a.w));
        __nv_bfloat162 h2 = __float22bfloat162_rn(make_float2(b.x, b.y));
        __nv_bfloat162 h3 = __float22bfloat162_rn(make_float2(b.z, b.w));
        ((uint4*)g_xb)[i] = make_uint4(*(uint32_t*)&h0, *(uint32_t*)&h1,
                                       *(uint32_t*)&h2, *(uint32_t*)&h3);
        return;
    }
    if (bid < XBLKS + ADJBLKS) {
        size_t i = (size_t)(bid - XBLKS) * 256 + tid;  // one per 8 floats
        int row = (int)((i * 8) / NN);                 // each thread's 8 elems in one row
        float sc = 0.125f / (1.0f + expf(-alpha[row]));
        const float4* src = (const float4*)adj + i * 2;
        float4 a = src[0], b = src[1];
        __nv_bfloat162 h0 = __float22bfloat162_rn(make_float2(a.x * sc, a.y * sc));
        __nv_bfloat162 h1 = __float22bfloat162_rn(make_float2(a.z * sc, a.w * sc));
        __nv_bfloat162 h2 = __float22bfloat162_rn(make_float2(b.x * sc, b.y * sc));
        __nv_bfloat162 h3 = __float22bfloat162_rn(make_float2(b.z * sc, b.w * sc));
        ((uint4*)g_adjb)[i] = make_uint4(*(uint32_t*)&h0, *(uint32_t*)&h1,
                                         *(uint32_t*)&h2, *(uint32_t*)&h3);
        return;
    }
    // prep block
    __shared__ float colsum[FA];
    __shared__ float dc[FA];
    if (tid < FA) {
        float s = 0.f;
        for (int n = 0; n < FA; n++) s += w[n * FA + tid];
        colsum[tid] = s;
        dc[tid] = fminf(fmaxf(d[tid], 0.f), 1.f);
    }
    __syncthreads();
    if (tid < FA) {
        float s = 0.f;
        for (int k = 0; k < FA; k++) s += w[tid * FA + k] * dc[k] * colsum[k];
        g_RW[tid] = s;
    }
    for (int idx = tid; idx < TT * TT; idx += 256) {
        int t = idx / TT, tp = idx % TT;
        float s = 0.f;
        for (int k = 0; k < TT; k++) {
            float dk = fminf(fmaxf(d2[k], 0.f), 1.f);
            s += w2[t * TT + k] * dk * w2[tp * TT + k];
        }
        g_W2[idx] = s;
    }
}

// ---------------------------------------------------------------------------
// GEMM: y[b,i,c] = sum_k adj_scaled[i,k]*x[b,k,c]  (bf16 in, fp32 acc, bf16 y)
// y is pre-scaled by 0.125*sigA[i] via adj. CTA 128x128, 4 warps, warp 64x64,
// 16 K-stages of 32, 4-stage cp.async; single barrier per stage.
// ---------------------------------------------------------------------------
__global__ __launch_bounds__(128, 2)
void gemm_kernel() {
    extern __shared__ char smem[];
    uint32_t sb = smem_u32(smem);

    int tid = threadIdx.x, l = tid & 31, wid = tid >> 5;
    int wm = wid & 1, wn = wid >> 1;
    int b = blockIdx.z, i0 = blockIdx.y * BM, c0 = blockIdx.x * BN;
    const __nv_bfloat16* Xb = g_xb + (size_t)b * NN * TF;

#define ISSUE_STAGE(s)                                                          \
    {                                                                           \
        int buf_ = (s) & (STAGES - 1);                                          \
        int k0_ = (s) * BK;                                                     \
        uint32_t ab_ = sb + buf_ * ASTGB;                                       \
        uint32_t bb_ = sb + STAGES * ASTGB + buf_ * BSTGB;                      \
        _Pragma("unroll")                                                       \
        for (int u = 0; u < 4; u++) {                                           \
            int id = u * 128 + tid;                                             \
            int ar = id >> 2, ac = id & 3;                                      \
            CP16(ab_ + ar * AROWB + ac * 16,                                    \
                 (const char*)(g_adjb + (size_t)(i0 + ar) * NN + k0_) + ac * 16); \
            int br = id >> 4, bc = id & 15;                                     \
            CP16(bb_ + br * BROWB + bc * 16,                                    \
                 (const char*)(Xb + (size_t)(k0_ + br) * TF + c0) + bc * 16);   \
        }                                                                       \
    }

    float acc[4][8][4];
    #pragma unroll
    for (int mt = 0; mt < 4; mt++)
        #pragma unroll
        for (int nt = 0; nt < 8; nt++)
            #pragma unroll
            for (int q = 0; q < 4; q++) acc[mt][nt][q] = 0.f;

    uint32_t a_off = (uint32_t)(wm * 64 + (l & 15)) * AROWB + ((l >> 4) * 8) * 2;
    uint32_t b_off = (uint32_t)(l & 15) * BROWB + (wn * 64 + ((l >> 4) << 3)) * 2;

    ISSUE_STAGE(0); CP_COMMIT();
    ISSUE_STAGE(1); CP_COMMIT();
    ISSUE_STAGE(2); CP_COMMIT();

    for (int s = 0; s < NKS; s++) {
        int buf = s & (STAGES - 1);
        CP_WAIT2();
        __syncthreads();

        if (s + 3 < NKS) ISSUE_STAGE(s + 3);
        CP_COMMIT();   // always commit so wait_group 2 tracks stage s exactly

        uint32_t ab = sb + buf * ASTGB + a_off;
        uint32_t bb = sb + STAGES * ASTGB + buf * BSTGB + b_off;
        #pragma unroll
        for (int ks = 0; ks < 2; ks++) {
            uint32_t af[4][4], bf[4][4];
            #pragma unroll
            for (int mt = 0; mt < 4; mt++)
                ldsm4(af[mt], ab + mt * 16 * AROWB + ks * 32);
            #pragma unroll
            for (int n2 = 0; n2 < 4; n2++)
                ldsm4t(bf[n2], bb + ks * 16 * BROWB + n2 * 32);
            #pragma unroll
            for (int mt = 0; mt < 4; mt++)
                #pragma unroll
                for (int nt = 0; nt < 8; nt++)
                    mma16816(acc[mt][nt], af[mt], &bf[nt >> 1][(nt & 1) * 2]);
        }
        // no trailing barrier — next iteration's top barrier protects the ring
    }

    // epilogue: fragments -> bf16 y
    int rbase = i0 + wm * 64 + (l >> 2);
    int cbase = c0 + wn * 64 + (l & 3) * 2;
    #pragma unroll
    for (int mt = 0; mt < 4; mt++) {
        #pragma unroll
        for (int nt = 0; nt < 8; nt++) {
            int i = rbase + mt * 16;
            int c = cbase + nt * 8;
            __nv_bfloat162 h0 = __float22bfloat162_rn(make_float2(acc[mt][nt][0], acc[mt][nt][1]));
            __nv_bfloat162 h1 = __float22bfloat162_rn(make_float2(acc[mt][nt][2], acc[mt][nt][3]));
            *(__nv_bfloat162*)&g_y[((size_t)b * NN + i) * TF + c] = h0;
            *(__nv_bfloat162*)&g_y[((size_t)b * NN + i + 8) * TF + c] = h1;
        }
    }
}

// ---------------------------------------------------------------------------
// Combine: 4 rows per block, 512 threads.
//   out = relu(0.5*x + 0.25*xw2 + 0.25*S*RW + y), plus f>=64 strip.
// (y already carries the 0.125*sigA scale.)
// ---------------------------------------------------------------------------
__global__ __launch_bounds__(512)
void combine_kernel(const float* __restrict__ x, float* __restrict__ out) {
    int row0 = blockIdx.x * 4;           // b*NN + node, 4 consecutive rows
    int tid = threadIdx.x;
    int ri = tid >> 7, sub = tid & 127;
    int row = row0 + ri;
    const float* xr = x + (size_t)row * TF;
    const __nv_bfloat16* yr = g_y + (size_t)row * TF;
    float* outr = out + (size_t)row * OUTROW;

    __shared__ float xs[4][TF];
    __shared__ float W2s[TT * TT];
    __shared__ float S[4][TT];
    __shared__ float RWs[FA];

    #pragma unroll
    for (int j = 0; j < 3; j++)
        ((float4*)xs[ri])[j * 128 + sub] = ((const float4*)xr)[j * 128 + sub];
    for (int j = tid; j < TT * TT; j += 512) W2s[j] = g_W2[j];
    if (tid < FA) RWs[tid] = g_RW[tid];
    __syncthreads();

    if (tid < 96) {
        int r = tid / 24;
        int t = tid - r * 24;
        float s = 0.f;
        #pragma unroll
        for (int f = 0; f < FF; f++) s += xs[r][t * FF + f];
        S[r][t] = s;
    }
    __syncthreads();

    int ty = sub >> 4, tx = sub & 15;
    float acc[3][4];
    #pragma unroll
    for (int r3 = 0; r3 < 3; r3++)
        #pragma unroll
        for (int q = 0; q < 4; q++) acc[r3][q] = 0.f;

    #pragma unroll
    for (int t = 0; t < TT; t++) {
        float4 xv = *(const float4*)&xs[ri][t * FF + tx * 4];
        float w0 = W2s[t * TT + ty];
        float w1 = W2s[t * TT + ty + 8];
        float w2v = W2s[t * TT + ty + 16];
        acc[0][0] = fmaf(w0, xv.x, acc[0][0]); acc[0][1] = fmaf(w0, xv.y, acc[0][1]);
        acc[0][2] = fmaf(w0, xv.z, acc[0][2]); acc[0][3] = fmaf(w0, xv.w, acc[0][3]);
        acc[1][0] = fmaf(w1, xv.x, acc[1][0]); acc[1][1] = fmaf(w1, xv.y, acc[1][1]);
        acc[1][2] = fmaf(w1, xv.z, acc[1][2]); acc[1][3] = fmaf(w1, xv.w, acc[1][3]);
        acc[2][0] = fmaf(w2v, xv.x, acc[2][0]); acc[2][1] = fmaf(w2v, xv.y, acc[2][1]);
        acc[2][2] = fmaf(w2v, xv.z, acc[2][2]); acc[2][3] = fmaf(w2v, xv.w, acc[2][3]);
    }

    #pragma unroll
    for (int r3 = 0; r3 < 3; r3++) {
        int tp = ty + r3 * 8;
        float sr = 0.25f * S[ri][tp];
        int f = tx * 4;
        uint2 ypk = *(const uint2*)&yr[tp * FF + f];
        __nv_bfloat162 yl = *(__nv_bfloat162*)&ypk.x;
        __nv_bfloat162 yh = *(__nv_bfloat162*)&ypk.y;
        float o0 = 0.5f * xs[ri][tp * FF + f]     + 0.25f * acc[r3][0] + sr * RWs[f]
                 + __bfloat162float(yl.x);
        float o1 = 0.5f * xs[ri][tp * FF + f + 1] + 0.25f * acc[r3][1] + sr * RWs[f + 1]
                 + __bfloat162float(yl.y);
        float o2 = 0.5f * xs[ri][tp * FF + f + 2] + 0.25f * acc[r3][2] + sr * RWs[f + 2]
                 + __bfloat162float(yh.x);
        float o3 = 0.5f * xs[ri][tp * FF + f + 3] + 0.25f * acc[r3][3] + sr * RWs[f + 3]
                 + __bfloat162float(yh.y);
        *(float2*)&outr[tp * FA + f]     = make_float2(fmaxf(o0, 0.f), fmaxf(o1, 0.f));
        *(float2*)&outr[tp * FA + f + 2] = make_float2(fmaxf(o2, 0.f), fmaxf(o3, 0.f));
    }
    // f >= 64 strip: 4 rows x 240 elems = 960 over 512 threads
    for (int idx = tid; idx < 4 * TT * (FA - FF); idx += 512) {
        int r = idx / (TT * (FA - FF));
        int e = idx - r * (TT * (FA - FF));
        int tp = e / (FA - FF);
        int f  = FF + e % (FA - FF);
        out[((size_t)(row0 + r)) * OUTROW + tp * FA + f] =
            fmaxf(0.25f * S[r][tp] * RWs[f], 0.f);
    }
}

extern "C" void kernel_launch(void* const* d_in, const int* in_sizes, int n_in,
                              void* d_out, int out_size) {
    const float* x     = (const float*)d_in[0];
    const float* adj   = (const float*)d_in[1];
    const float* alpha = (const float*)d_in[2];
    const float* w     = (const float*)d_in[3];
    const float* d     = (const float*)d_in[4];
    const float* w2    = (const float*)d_in[5];
    const float* d2    = (const float*)d_in[6];
    float* out = (float*)d_out;

    cudaFuncSetAttribute(gemm_kernel, cudaFuncAttributeMaxDynamicSharedMemorySize, GEMM_SMEM);

    pre_kernel<<<XBLKS + ADJBLKS + 1, 256>>>(x, adj, alpha, w, d, w2, d2);
    dim3 grid(TF / BN, NN / BM, B_);
    gemm_kernel<<<grid, 128, GEMM_SMEM>>>();
    combine_kernel<<<B_ * NN / 4, 512>>>(x, out);
}